// round 1
// baseline (speedup 1.0000x reference)
#include <cuda_runtime.h>
#include <math.h>

#define NB   256     // batch
#define NT   128     // seq len
#define VOC  42
#define LATD 200
#define UU   512
#define PP   3
#define BT   (NB*NT)       // 32768
#define G4U  2048          // 4*U

// ---------------- device scratch (no allocations allowed) ----------------
__device__ float g_bufA[(size_t)BT*UU];        // 64 MB  ping
__device__ float g_bufB[(size_t)BT*UU];        // 64 MB  pong
__device__ float g_Z[(size_t)BT*G4U];          // 268 MB precomputed x@k + bias
__device__ float g_c[NB*UU];                   // cell state
__device__ float g_mean[NB*LATD];
__device__ float g_ls[NB*LATD];
__device__ float g_zlat[NB*LATD];
__device__ float g_acc[2];                     // [0]=recon sum, [1]=latent sum

// ---------------- tiny utility kernels ----------------
__global__ void k_zero(float* p, int n) {
    int i = blockIdx.x * blockDim.x + threadIdx.x;
    if (i < n) p[i] = 0.f;
}

// encoder input: row bt = [emb_enc[X[bt]] (200), C[b] (3)]  (stride UU)
__global__ void k_build_enc(const int* __restrict__ X, const float* __restrict__ emb,
                            const float* __restrict__ C, float* __restrict__ out) {
    int bt = blockIdx.x;
    int b = bt / NT;
    float* row = out + (size_t)bt * UU;
    int x = X[bt];
    for (int i = threadIdx.x; i < LATD; i += blockDim.x)
        row[i] = emb[x * LATD + i];
    if (threadIdx.x < PP)
        row[LATD + threadIdx.x] = C[b * PP + threadIdx.x];
}

// decoder input: row bt = [z[b] (200), emb_dec[X[bt]] (200), C[b] (3)]
__global__ void k_build_dec(const int* __restrict__ X, const float* __restrict__ emb,
                            const float* __restrict__ C, const float* __restrict__ zl,
                            float* __restrict__ out) {
    int bt = blockIdx.x;
    int b = bt / NT;
    float* row = out + (size_t)bt * UU;
    int x = X[bt];
    for (int i = threadIdx.x; i < LATD; i += blockDim.x) {
        row[i]        = zl[b * LATD + i];
        row[LATD + i] = emb[x * LATD + i];
    }
    if (threadIdx.x < PP)
        row[2 * LATD + threadIdx.x] = C[b * PP + threadIdx.x];
}

// ---------------- big GEMM: C[M,N] = A[M,K](lda) @ W[K,N] + bias[N] ----------------
// 128x128 tile, KC=8, 8x8 per thread, 256 threads.
__global__ void k_gemm(const float* __restrict__ A, int lda,
                       const float* __restrict__ W, const float* __restrict__ bias,
                       float* __restrict__ Co, int ldc, int M, int N, int K) {
    __shared__ float As[8][132];
    __shared__ float Bs[8][132];
    int tx = threadIdx.x;
    int row0 = blockIdx.y * 128, col0 = blockIdx.x * 128;
    int trow = (tx >> 4) * 8, tcol = (tx & 15) * 8;
    float acc[8][8];
#pragma unroll
    for (int i = 0; i < 8; i++)
#pragma unroll
        for (int j = 0; j < 8; j++) acc[i][j] = 0.f;

    for (int kk = 0; kk < K; kk += 8) {
        for (int i = tx; i < 128 * 8; i += 256) {
            int r = i >> 3, c = i & 7;
            int gk = kk + c;
            As[c][r] = (gk < K) ? A[(size_t)(row0 + r) * lda + gk] : 0.f;
        }
        for (int i = tx; i < 8 * 128; i += 256) {
            int r = i >> 7, c = i & 127;
            int gk = kk + r;
            Bs[r][c] = (gk < K) ? W[(size_t)gk * N + col0 + c] : 0.f;
        }
        __syncthreads();
#pragma unroll
        for (int k = 0; k < 8; k++) {
            float a[8], bb[8];
#pragma unroll
            for (int i = 0; i < 8; i++) a[i] = As[k][trow + i];
#pragma unroll
            for (int j = 0; j < 8; j++) bb[j] = Bs[k][tcol + j];
#pragma unroll
            for (int i = 0; i < 8; i++)
#pragma unroll
                for (int j = 0; j < 8; j++) acc[i][j] += a[i] * bb[j];
        }
        __syncthreads();
    }
#pragma unroll
    for (int i = 0; i < 8; i++) {
        size_t r = (size_t)(row0 + trow + i);
#pragma unroll
        for (int j = 0; j < 8; j++) {
            int cc = col0 + tcol + j;
            Co[r * ldc + cc] = acc[i][j] + bias[cc];
        }
    }
}

// ---------------- fused LSTM recurrent step ----------------
// grid (8 u-blocks of 64, 16 b-blocks of 16), 256 threads.
// Each thread: 4 batches x 4 gates of one u. z = Z (precomputed x@k+b) + h@rk.
__device__ __forceinline__ float sigm(float x) { return 1.f / (1.f + expf(-x)); }

__global__ void k_lstm_step(const float* __restrict__ Z, const float* __restrict__ rk,
                            const float* __restrict__ hprev, float* __restrict__ hout,
                            float* __restrict__ cst, int t) {
    __shared__ float hs[16][64];
    int lane_u = threadIdx.x & 63;
    int lb = threadIdx.x >> 6;          // 0..3
    int u = blockIdx.x * 64 + lane_u;
    int b0 = blockIdx.y * 16;

    float acc[4][4];
#pragma unroll
    for (int i = 0; i < 4; i++)
#pragma unroll
        for (int g = 0; g < 4; g++) acc[i][g] = 0.f;

    if (hprev) {
        for (int kk = 0; kk < UU; kk += 64) {
            __syncthreads();
            for (int i = threadIdx.x; i < 16 * 64; i += 256) {
                int r = i >> 6, c = i & 63;
                hs[r][c] = hprev[((size_t)((b0 + r) * NT + (t - 1))) * UU + kk + c];
            }
            __syncthreads();
#pragma unroll 8
            for (int k = 0; k < 64; k++) {
                const float* rp = rk + (size_t)(kk + k) * G4U + u;
                float w0 = rp[0], w1 = rp[512], w2 = rp[1024], w3 = rp[1536];
#pragma unroll
                for (int bi = 0; bi < 4; bi++) {
                    float hv = hs[lb * 4 + bi][k];
                    acc[bi][0] += hv * w0;
                    acc[bi][1] += hv * w1;
                    acc[bi][2] += hv * w2;
                    acc[bi][3] += hv * w3;
                }
            }
        }
    }
#pragma unroll
    for (int bi = 0; bi < 4; bi++) {
        int b = b0 + lb * 4 + bi;
        const float* zr = Z + (size_t)(b * NT + t) * G4U;
        float zi = zr[u]        + acc[bi][0];
        float zf = zr[512 + u]  + acc[bi][1];
        float zg = zr[1024 + u] + acc[bi][2];
        float zo = zr[1536 + u] + acc[bi][3];
        float co = cst[b * UU + u];
        float c2 = sigm(zf) * co + sigm(zi) * tanhf(zg);
        float h2 = sigm(zo) * tanhf(c2);
        cst[b * UU + u] = c2;
        hout[(size_t)(b * NT + t) * UU + u] = h2;
    }
}

// ---------------- mean / log_sigma / reparameterize ----------------
__global__ void k_mean_ls(const float* __restrict__ cst,
                          const float* __restrict__ Wm, const float* __restrict__ bm,
                          const float* __restrict__ Ws, const float* __restrict__ bs,
                          const float* __restrict__ eps,
                          float* __restrict__ mo, float* __restrict__ lo, float* __restrict__ zo) {
    int idx = blockIdx.x * blockDim.x + threadIdx.x;
    if (idx >= NB * LATD) return;
    int b = idx / LATD, l = idx % LATD;
    const float* cr = cst + b * UU;
    float m = bm[l], s = bs[l];
    for (int k = 0; k < UU; k++) {
        float cv = cr[k];
        m += cv * Wm[k * LATD + l];
        s += cv * Ws[k * LATD + l];
    }
    mo[idx] = m;
    lo[idx] = s;
    zo[idx] = m + expf(0.5f * s) * eps[idx];
}

// ---------------- latent KL partial-sum ----------------
__global__ void k_latent(const float* __restrict__ mo, const float* __restrict__ lo,
                         float* __restrict__ acc) {
    __shared__ float sdata[256];
    int idx = blockIdx.x * blockDim.x + threadIdx.x;
    float v = 0.f;
    if (idx < NB * LATD) {
        float m = mo[idx], s = lo[idx];
        v = 1.f + s - m * m - expf(s);
    }
    sdata[threadIdx.x] = v;
    __syncthreads();
    for (int o = 128; o > 0; o >>= 1) {
        if (threadIdx.x < o) sdata[threadIdx.x] += sdata[threadIdx.x + o];
        __syncthreads();
    }
    if (threadIdx.x == 0) atomicAdd(acc + 1, sdata[0]);
}

// ---------------- fused output projection + log-softmax + masked CE ----------------
// one warp per (b,t) row; 8 rows per block.
__global__ void k_ce(const float* __restrict__ H, const float* __restrict__ Wo,
                     const float* __restrict__ bo, const int* __restrict__ Y,
                     const int* __restrict__ L, float* __restrict__ acc) {
    __shared__ float hs[8][UU];
    int row0 = blockIdx.x * 8;
    for (int i = threadIdx.x; i < 8 * UU; i += 256) {
        int r = i >> 9, k = i & 511;
        hs[r][k] = H[(size_t)(row0 + r) * UU + k];
    }
    __syncthreads();
    int w = threadIdx.x >> 5, lane = threadIdx.x & 31;
    int row = row0 + w;
    int b = row / NT, t = row % NT;

    float d0 = 0.f, d1 = 0.f;
    bool has1 = (lane + 32) < VOC;
    for (int k = 0; k < UU; k++) {
        float hv = hs[w][k];
        d0 += hv * Wo[k * VOC + lane];
        if (has1) d1 += hv * Wo[k * VOC + lane + 32];
    }
    float p0 = d0 + bo[lane];
    float p1 = has1 ? (d1 + bo[lane + 32]) : -1e30f;
    float m = fmaxf(p0, p1);
#pragma unroll
    for (int o = 16; o; o >>= 1) m = fmaxf(m, __shfl_xor_sync(0xffffffffu, m, o));
    float e = expf(p0 - m) + (has1 ? expf(p1 - m) : 0.f);
#pragma unroll
    for (int o = 16; o; o >>= 1) e += __shfl_xor_sync(0xffffffffu, e, o);
    float lse = logf(e) + m;
    int y = Y[row];
    float py = __shfl_sync(0xffffffffu, (y < 32) ? p0 : p1, y & 31);
    if (lane == 0) {
        float wt = (t < L[b]) ? 1.f : 0.f;
        atomicAdd(acc, (lse - py) * wt);
    }
}

__global__ void k_final(const float* __restrict__ acc, float* __restrict__ out, int out_size) {
    if (threadIdx.x == 0) {
        float recon = acc[0] / (float)BT;
        float lat = -0.5f * acc[1] / (float)(NB * LATD);
        if (out_size > 0) out[0] = recon + lat;
        if (out_size > 1) out[1] = recon;
        if (out_size > 2) out[2] = lat;
    }
}

// ---------------- host driver ----------------
extern "C" void kernel_launch(void* const* d_in, const int* in_sizes, int n_in,
                              void* d_out, int out_size) {
    const int*   X       = (const int*)d_in[0];
    const int*   Y       = (const int*)d_in[1];
    const float* C       = (const float*)d_in[2];
    const int*   L       = (const int*)d_in[3];
    const float* eps     = (const float*)d_in[4];
    const float* emb_enc = (const float*)d_in[5];
    const float* emb_dec = (const float*)d_in[6];
    const float* enc_k[3]  = {(const float*)d_in[7],  (const float*)d_in[10], (const float*)d_in[13]};
    const float* enc_rk[3] = {(const float*)d_in[8],  (const float*)d_in[11], (const float*)d_in[14]};
    const float* enc_b[3]  = {(const float*)d_in[9],  (const float*)d_in[12], (const float*)d_in[15]};
    const float* dec_k[3]  = {(const float*)d_in[16], (const float*)d_in[19], (const float*)d_in[22]};
    const float* dec_rk[3] = {(const float*)d_in[17], (const float*)d_in[20], (const float*)d_in[23]};
    const float* dec_b[3]  = {(const float*)d_in[18], (const float*)d_in[21], (const float*)d_in[24]};
    const float* Wm = (const float*)d_in[25];
    const float* bm = (const float*)d_in[26];
    const float* Ws = (const float*)d_in[27];
    const float* bs = (const float*)d_in[28];
    const float* Wo = (const float*)d_in[29];
    const float* bo = (const float*)d_in[30];

    float *bufA, *bufB, *Zb, *cst, *mo, *lo, *zl, *acc;
    cudaGetSymbolAddress((void**)&bufA, g_bufA);
    cudaGetSymbolAddress((void**)&bufB, g_bufB);
    cudaGetSymbolAddress((void**)&Zb,   g_Z);
    cudaGetSymbolAddress((void**)&cst,  g_c);
    cudaGetSymbolAddress((void**)&mo,   g_mean);
    cudaGetSymbolAddress((void**)&lo,   g_ls);
    cudaGetSymbolAddress((void**)&zl,   g_zlat);
    cudaGetSymbolAddress((void**)&acc,  g_acc);

    k_zero<<<1, 64>>>(acc, 2);

    dim3 gemm_grid(G4U / 128, BT / 128);
    dim3 step_grid(8, 16);

    // ======== encoder ========
    k_build_enc<<<BT, 256>>>(X, emb_enc, C, bufA);
    {
        const int Ks[3] = {LATD + PP, UU, UU};
        float* inb = bufA;
        float* outb = bufB;
        for (int l = 0; l < 3; l++) {
            k_gemm<<<gemm_grid, 256>>>(inb, UU, enc_k[l], enc_b[l], Zb, G4U, BT, G4U, Ks[l]);
            k_zero<<<(NB * UU + 255) / 256, 256>>>(cst, NB * UU);
            for (int t = 0; t < NT; t++)
                k_lstm_step<<<step_grid, 256>>>(Zb, enc_rk[l],
                                                (t == 0) ? (const float*)nullptr : outb,
                                                outb, cst, t);
            float* tmp = inb; inb = outb; outb = tmp;
        }
    }
    // g_c now holds final cell state of encoder layer 2
    k_mean_ls<<<(NB * LATD + 255) / 256, 256>>>(cst, Wm, bm, Ws, bs, eps, mo, lo, zl);
    k_latent<<<(NB * LATD + 255) / 256, 256>>>(mo, lo, acc);

    // ======== decoder ========
    k_build_dec<<<BT, 256>>>(X, emb_dec, C, zl, bufA);
    float* dec_h = nullptr;
    {
        const int Ks[3] = {2 * LATD + PP, UU, UU};
        float* inb = bufA;
        float* outb = bufB;
        for (int l = 0; l < 3; l++) {
            k_gemm<<<gemm_grid, 256>>>(inb, UU, dec_k[l], dec_b[l], Zb, G4U, BT, G4U, Ks[l]);
            k_zero<<<(NB * UU + 255) / 256, 256>>>(cst, NB * UU);
            for (int t = 0; t < NT; t++)
                k_lstm_step<<<step_grid, 256>>>(Zb, dec_rk[l],
                                                (t == 0) ? (const float*)nullptr : outb,
                                                outb, cst, t);
            float* tmp = inb; inb = outb; outb = tmp;
        }
        dec_h = inb;  // final layer's h sequence
    }

    // ======== losses ========
    k_ce<<<BT / 8, 256>>>(dec_h, Wo, bo, Y, L, acc);
    k_final<<<1, 32>>>(acc, (float*)d_out, out_size);
}

// round 2
// speedup vs baseline: 2.1111x; 2.1111x over previous
#include <cuda_runtime.h>
#include <math.h>

#define NB   256     // batch
#define NT   128     // seq len
#define VOC  42
#define LATD 200
#define UU   512
#define PP   3
#define BT   (NB*NT)       // 32768
#define G4U  2048          // 4*U

// ---------------- device scratch ----------------
__device__ float g_bufA[(size_t)BT*UU];
__device__ float g_bufB[(size_t)BT*UU];
__device__ float g_Z[(size_t)BT*G4U];
__device__ float g_c[NB*UU];
__device__ float g_mean[NB*LATD];
__device__ float g_ls[NB*LATD];
__device__ float g_zlat[NB*LATD];
__device__ float g_acc[2];

// ---------------- helpers ----------------
__device__ __forceinline__ unsigned f2tf32(float x) {
    unsigned r;
    asm("cvt.rna.tf32.f32 %0, %1;" : "=r"(r) : "f"(x));
    return r;
}
__device__ __forceinline__ void mma_tf32(float c[4], const unsigned a[4], const unsigned b[2]) {
    asm volatile(
        "mma.sync.aligned.m16n8k8.row.col.f32.tf32.tf32.f32 "
        "{%0,%1,%2,%3}, {%4,%5,%6,%7}, {%8,%9}, {%0,%1,%2,%3};\n"
        : "+f"(c[0]), "+f"(c[1]), "+f"(c[2]), "+f"(c[3])
        : "r"(a[0]), "r"(a[1]), "r"(a[2]), "r"(a[3]), "r"(b[0]), "r"(b[1]));
}
__device__ __forceinline__ float sigm(float x) { return 1.f / (1.f + expf(-x)); }

// ---------------- tiny utility kernels ----------------
__global__ void k_zero(float* p, int n) {
    int i = blockIdx.x * blockDim.x + threadIdx.x;
    if (i < n) p[i] = 0.f;
}

__global__ void k_build_enc(const int* __restrict__ X, const float* __restrict__ emb,
                            const float* __restrict__ C, float* __restrict__ out) {
    int bt = blockIdx.x;
    int b = bt / NT;
    float* row = out + (size_t)bt * UU;
    int x = X[bt];
    for (int i = threadIdx.x; i < LATD; i += blockDim.x)
        row[i] = emb[x * LATD + i];
    if (threadIdx.x < PP)
        row[LATD + threadIdx.x] = C[b * PP + threadIdx.x];
}

__global__ void k_build_dec(const int* __restrict__ X, const float* __restrict__ emb,
                            const float* __restrict__ C, const float* __restrict__ zl,
                            float* __restrict__ out) {
    int bt = blockIdx.x;
    int b = bt / NT;
    float* row = out + (size_t)bt * UU;
    int x = X[bt];
    for (int i = threadIdx.x; i < LATD; i += blockDim.x) {
        row[i]        = zl[b * LATD + i];
        row[LATD + i] = emb[x * LATD + i];
    }
    if (threadIdx.x < PP)
        row[2 * LATD + threadIdx.x] = C[b * PP + threadIdx.x];
}

// ---------------- big GEMM (tf32 tensor core) ----------------
// C[M,N] = A[M,K](lda, fp32) @ W[K,N](fp32) + bias. 128x128x16 tile, 8 warps (4m x 2n).
__global__ __launch_bounds__(256) void k_gemm_tc(
    const float* __restrict__ A, int lda,
    const float* __restrict__ W, const float* __restrict__ bias,
    float* __restrict__ Co, int ldc, int M, int N, int K) {
    __shared__ unsigned As[16][132];  // [k][m]
    __shared__ unsigned Bs[16][132];  // [k][n]
    int tid = threadIdx.x;
    int wid = tid >> 5, lane = tid & 31;
    int wm = wid >> 1, wn = wid & 1;       // 4 x 2
    int lq = lane >> 2, lr = lane & 3;
    int row0 = blockIdx.y * 128, col0 = blockIdx.x * 128;

    float c[2][8][4];
#pragma unroll
    for (int mt = 0; mt < 2; mt++)
#pragma unroll
        for (int nt = 0; nt < 8; nt++)
#pragma unroll
            for (int j = 0; j < 4; j++) c[mt][nt][j] = 0.f;

    for (int kk = 0; kk < K; kk += 16) {
#pragma unroll
        for (int i = tid; i < 128 * 16; i += 256) {
            int r = i >> 4, cc = i & 15;
            float v = (kk + cc < K) ? A[(size_t)(row0 + r) * lda + kk + cc] : 0.f;
            As[cc][r] = f2tf32(v);
        }
#pragma unroll
        for (int i = tid; i < 16 * 128; i += 256) {
            int r = i >> 7, cc = i & 127;
            float v = (kk + r < K) ? W[(size_t)(kk + r) * N + col0 + cc] : 0.f;
            Bs[r][cc] = f2tf32(v);
        }
        __syncthreads();
#pragma unroll
        for (int ks = 0; ks < 2; ks++) {
            int kb = ks * 8;
            unsigned af[2][4];
#pragma unroll
            for (int mt = 0; mt < 2; mt++) {
                int mb = wm * 32 + mt * 16;
                af[mt][0] = As[kb + lr][mb + lq];
                af[mt][1] = As[kb + lr][mb + lq + 8];
                af[mt][2] = As[kb + lr + 4][mb + lq];
                af[mt][3] = As[kb + lr + 4][mb + lq + 8];
            }
#pragma unroll
            for (int nt = 0; nt < 8; nt++) {
                int nb = wn * 64 + nt * 8;
                unsigned bf[2];
                bf[0] = Bs[kb + lr][nb + lq];
                bf[1] = Bs[kb + lr + 4][nb + lq];
#pragma unroll
                for (int mt = 0; mt < 2; mt++) mma_tf32(c[mt][nt], af[mt], bf);
            }
        }
        __syncthreads();
    }
#pragma unroll
    for (int mt = 0; mt < 2; mt++) {
        size_t rb = (size_t)(row0 + wm * 32 + mt * 16 + lq);
#pragma unroll
        for (int nt = 0; nt < 8; nt++) {
            int cb = col0 + wn * 64 + nt * 8 + 2 * lr;
            float b0 = bias[cb], b1 = bias[cb + 1];
            Co[rb * ldc + cb]           = c[mt][nt][0] + b0;
            Co[rb * ldc + cb + 1]       = c[mt][nt][1] + b1;
            Co[(rb + 8) * ldc + cb]     = c[mt][nt][2] + b0;
            Co[(rb + 8) * ldc + cb + 1] = c[mt][nt][3] + b1;
        }
    }
}

// ---------------- fused LSTM step (tf32 tensor core) ----------------
// grid (16 u-blocks of 32, 8 b-blocks of 32), 256 threads (8 warps: 2m x 4n).
// Block computes z' = hprev[32b x 512] @ rk[:, 4 gate panels of 32u] (32x128),
// recombines gates via smem, applies LSTM update with precomputed Z.
__global__ __launch_bounds__(256) void k_step_tc(
    const float* __restrict__ Z, const float* __restrict__ rk,
    const float* __restrict__ hprev, float* __restrict__ hout,
    float* __restrict__ cst, int t) {
    __shared__ float smem[32 * 132];                 // zsm[32][132] (reused)
    unsigned* As = (unsigned*)smem;                  // [16][36]
    unsigned* Bs = (unsigned*)smem + 16 * 36;        // [16][132]

    int tid = threadIdx.x;
    int wid = tid >> 5, lane = tid & 31;
    int wm = wid >> 2, wn = wid & 3;                 // 2 x 4
    int lq = lane >> 2, lr = lane & 3;
    int u0 = blockIdx.x * 32;
    int b0 = blockIdx.y * 32;

    float c[4][4];
#pragma unroll
    for (int nt = 0; nt < 4; nt++)
#pragma unroll
        for (int j = 0; j < 4; j++) c[nt][j] = 0.f;

    if (hprev) {
        for (int kk = 0; kk < UU; kk += 16) {
#pragma unroll
            for (int i = tid; i < 32 * 16; i += 256) {
                int r = i >> 4, cc = i & 15;
                As[cc * 36 + r] =
                    f2tf32(hprev[((size_t)(b0 + r) * NT + (t - 1)) * UU + kk + cc]);
            }
#pragma unroll
            for (int i = tid; i < 16 * 128; i += 256) {
                int r = i >> 7, cc = i & 127;
                Bs[r * 132 + cc] =
                    f2tf32(rk[(size_t)(kk + r) * G4U + (cc >> 5) * 512 + u0 + (cc & 31)]);
            }
            __syncthreads();
#pragma unroll
            for (int ks = 0; ks < 2; ks++) {
                int kb = ks * 8;
                int mb = wm * 16;
                unsigned af[4];
                af[0] = As[(kb + lr) * 36 + mb + lq];
                af[1] = As[(kb + lr) * 36 + mb + lq + 8];
                af[2] = As[(kb + lr + 4) * 36 + mb + lq];
                af[3] = As[(kb + lr + 4) * 36 + mb + lq + 8];
#pragma unroll
                for (int nt = 0; nt < 4; nt++) {
                    int nb = wn * 32 + nt * 8;
                    unsigned bf[2];
                    bf[0] = Bs[(kb + lr) * 132 + nb + lq];
                    bf[1] = Bs[(kb + lr + 4) * 132 + nb + lq];
                    mma_tf32(c[nt], af, bf);
                }
            }
            __syncthreads();
        }
    }

    // scatter C frags to zsm[32][132]  (col = gate*32 + ulocal)
    float* zsm = smem;
    {
        int rb = wm * 16 + lq;
#pragma unroll
        for (int nt = 0; nt < 4; nt++) {
            int cb = wn * 32 + nt * 8 + 2 * lr;
            zsm[rb * 132 + cb]           = c[nt][0];
            zsm[rb * 132 + cb + 1]       = c[nt][1];
            zsm[(rb + 8) * 132 + cb]     = c[nt][2];
            zsm[(rb + 8) * 132 + cb + 1] = c[nt][3];
        }
    }
    __syncthreads();

    // LSTM update: 32x32 (b,u) outputs, 4 per thread
#pragma unroll
    for (int rep = 0; rep < 4; rep++) {
        int e = rep * 256 + tid;
        int bl = e >> 5, ul = e & 31;
        int b = b0 + bl, u = u0 + ul;
        const float* zr = Z + ((size_t)b * NT + t) * G4U + u0 + ul;
        float zi = zsm[bl * 132 + ul]       + zr[0];
        float zf = zsm[bl * 132 + 32 + ul]  + zr[512];
        float zg = zsm[bl * 132 + 64 + ul]  + zr[1024];
        float zo = zsm[bl * 132 + 96 + ul]  + zr[1536];
        float co = hprev ? cst[b * UU + u] : 0.f;
        float c2 = sigm(zf) * co + sigm(zi) * tanhf(zg);
        float h2 = sigm(zo) * tanhf(c2);
        cst[b * UU + u] = c2;
        hout[((size_t)b * NT + t) * UU + u] = h2;
    }
}

// ---------------- mean / log_sigma / reparameterize ----------------
__global__ void k_mean_ls(const float* __restrict__ cst,
                          const float* __restrict__ Wm, const float* __restrict__ bm,
                          const float* __restrict__ Ws, const float* __restrict__ bs,
                          const float* __restrict__ eps,
                          float* __restrict__ mo, float* __restrict__ lo, float* __restrict__ zo) {
    int idx = blockIdx.x * blockDim.x + threadIdx.x;
    if (idx >= NB * LATD) return;
    int b = idx / LATD, l = idx % LATD;
    const float* cr = cst + b * UU;
    float m = bm[l], s = bs[l];
    for (int k = 0; k < UU; k++) {
        float cv = cr[k];
        m += cv * Wm[k * LATD + l];
        s += cv * Ws[k * LATD + l];
    }
    mo[idx] = m;
    lo[idx] = s;
    zo[idx] = m + expf(0.5f * s) * eps[idx];
}

__global__ void k_latent(const float* __restrict__ mo, const float* __restrict__ lo,
                         float* __restrict__ acc) {
    __shared__ float sdata[256];
    int idx = blockIdx.x * blockDim.x + threadIdx.x;
    float v = 0.f;
    if (idx < NB * LATD) {
        float m = mo[idx], s = lo[idx];
        v = 1.f + s - m * m - expf(s);
    }
    sdata[threadIdx.x] = v;
    __syncthreads();
    for (int o = 128; o > 0; o >>= 1) {
        if (threadIdx.x < o) sdata[threadIdx.x] += sdata[threadIdx.x + o];
        __syncthreads();
    }
    if (threadIdx.x == 0) atomicAdd(acc + 1, sdata[0]);
}

// ---------------- fused logits + log-softmax + masked CE ----------------
__global__ void k_ce(const float* __restrict__ H, const float* __restrict__ Wo,
                     const float* __restrict__ bo, const int* __restrict__ Y,
                     const int* __restrict__ L, float* __restrict__ acc) {
    __shared__ float hs[8][UU];
    int row0 = blockIdx.x * 8;
    for (int i = threadIdx.x; i < 8 * UU; i += 256) {
        int r = i >> 9, k = i & 511;
        hs[r][k] = H[(size_t)(row0 + r) * UU + k];
    }
    __syncthreads();
    int w = threadIdx.x >> 5, lane = threadIdx.x & 31;
    int row = row0 + w;
    int b = row / NT, t = row % NT;

    float d0 = 0.f, d1 = 0.f;
    bool has1 = (lane + 32) < VOC;
    for (int k = 0; k < UU; k++) {
        float hv = hs[w][k];
        d0 += hv * Wo[k * VOC + lane];
        if (has1) d1 += hv * Wo[k * VOC + lane + 32];
    }
    float p0 = d0 + bo[lane];
    float p1 = has1 ? (d1 + bo[lane + 32]) : -1e30f;
    float m = fmaxf(p0, p1);
#pragma unroll
    for (int o = 16; o; o >>= 1) m = fmaxf(m, __shfl_xor_sync(0xffffffffu, m, o));
    float e = expf(p0 - m) + (has1 ? expf(p1 - m) : 0.f);
#pragma unroll
    for (int o = 16; o; o >>= 1) e += __shfl_xor_sync(0xffffffffu, e, o);
    float lse = logf(e) + m;
    int y = Y[row];
    float py = __shfl_sync(0xffffffffu, (y < 32) ? p0 : p1, y & 31);
    if (lane == 0) {
        float wt = (t < L[b]) ? 1.f : 0.f;
        atomicAdd(acc, (lse - py) * wt);
    }
}

__global__ void k_final(const float* __restrict__ acc, float* __restrict__ out, int out_size) {
    if (threadIdx.x == 0) {
        float recon = acc[0] / (float)BT;
        float lat = -0.5f * acc[1] / (float)(NB * LATD);
        if (out_size > 0) out[0] = recon + lat;
        if (out_size > 1) out[1] = recon;
        if (out_size > 2) out[2] = lat;
    }
}

// ---------------- host driver ----------------
extern "C" void kernel_launch(void* const* d_in, const int* in_sizes, int n_in,
                              void* d_out, int out_size) {
    const int*   X       = (const int*)d_in[0];
    const int*   Y       = (const int*)d_in[1];
    const float* C       = (const float*)d_in[2];
    const int*   L       = (const int*)d_in[3];
    const float* eps     = (const float*)d_in[4];
    const float* emb_enc = (const float*)d_in[5];
    const float* emb_dec = (const float*)d_in[6];
    const float* enc_k[3]  = {(const float*)d_in[7],  (const float*)d_in[10], (const float*)d_in[13]};
    const float* enc_rk[3] = {(const float*)d_in[8],  (const float*)d_in[11], (const float*)d_in[14]};
    const float* enc_b[3]  = {(const float*)d_in[9],  (const float*)d_in[12], (const float*)d_in[15]};
    const float* dec_k[3]  = {(const float*)d_in[16], (const float*)d_in[19], (const float*)d_in[22]};
    const float* dec_rk[3] = {(const float*)d_in[17], (const float*)d_in[20], (const float*)d_in[23]};
    const float* dec_b[3]  = {(const float*)d_in[18], (const float*)d_in[21], (const float*)d_in[24]};
    const float* Wm = (const float*)d_in[25];
    const float* bm = (const float*)d_in[26];
    const float* Ws = (const float*)d_in[27];
    const float* bs = (const float*)d_in[28];
    const float* Wo = (const float*)d_in[29];
    const float* bo = (const float*)d_in[30];

    float *bufA, *bufB, *Zb, *cst, *mo, *lo, *zl, *acc;
    cudaGetSymbolAddress((void**)&bufA, g_bufA);
    cudaGetSymbolAddress((void**)&bufB, g_bufB);
    cudaGetSymbolAddress((void**)&Zb,   g_Z);
    cudaGetSymbolAddress((void**)&cst,  g_c);
    cudaGetSymbolAddress((void**)&mo,   g_mean);
    cudaGetSymbolAddress((void**)&lo,   g_ls);
    cudaGetSymbolAddress((void**)&zl,   g_zlat);
    cudaGetSymbolAddress((void**)&acc,  g_acc);

    k_zero<<<1, 64>>>(acc, 2);

    dim3 gemm_grid(G4U / 128, BT / 128);
    dim3 step_grid(16, 8);

    // ======== encoder ========
    k_build_enc<<<BT, 256>>>(X, emb_enc, C, bufA);
    {
        const int Ks[3] = {LATD + PP, UU, UU};
        float* inb = bufA;
        float* outb = bufB;
        for (int l = 0; l < 3; l++) {
            k_gemm_tc<<<gemm_grid, 256>>>(inb, UU, enc_k[l], enc_b[l], Zb, G4U, BT, G4U, Ks[l]);
            for (int t = 0; t < NT; t++)
                k_step_tc<<<step_grid, 256>>>(Zb, enc_rk[l],
                                              (t == 0) ? (const float*)nullptr : outb,
                                              outb, cst, t);
            float* tmp = inb; inb = outb; outb = tmp;
        }
    }
    k_mean_ls<<<(NB * LATD + 255) / 256, 256>>>(cst, Wm, bm, Ws, bs, eps, mo, lo, zl);
    k_latent<<<(NB * LATD + 255) / 256, 256>>>(mo, lo, acc);

    // ======== decoder ========
    k_build_dec<<<BT, 256>>>(X, emb_dec, C, zl, bufA);
    float* dec_h = nullptr;
    {
        const int Ks[3] = {2 * LATD + PP, UU, UU};
        float* inb = bufA;
        float* outb = bufB;
        for (int l = 0; l < 3; l++) {
            k_gemm_tc<<<gemm_grid, 256>>>(inb, UU, dec_k[l], dec_b[l], Zb, G4U, BT, G4U, Ks[l]);
            for (int t = 0; t < NT; t++)
                k_step_tc<<<step_grid, 256>>>(Zb, dec_rk[l],
                                              (t == 0) ? (const float*)nullptr : outb,
                                              outb, cst, t);
            float* tmp = inb; inb = outb; outb = tmp;
        }
        dec_h = inb;
    }

    // ======== losses ========
    k_ce<<<BT / 8, 256>>>(dec_h, Wo, bo, Y, L, acc);
    k_final<<<1, 32>>>(acc, (float*)d_out, out_size);
}

// round 3
// speedup vs baseline: 4.8843x; 2.3136x over previous
#include <cuda_runtime.h>
#include <cuda_bf16.h>
#include <math.h>

#define NB   256
#define NT   128
#define VOC  42
#define LATD 200
#define UU   512
#define PP   3
#define BT   (NB*NT)
#define G4U  2048
#define SCAN_BLOCKS 128

// ---------------- device scratch ----------------
__device__ __nv_bfloat16 g_bufA[(size_t)BT*UU];   // 32 MB
__device__ __nv_bfloat16 g_bufB[(size_t)BT*UU];   // 32 MB
__device__ float g_Z[(size_t)BT*G4U];             // 268 MB
__device__ __nv_bfloat16 g_wt[(size_t)G4U*UU];    // weight^T bf16
__device__ __nv_bfloat16 g_rkt[(size_t)G4U*UU];   // rk^T bf16
__device__ float g_c[NB*UU];
__device__ float g_mean[NB*LATD];
__device__ float g_ls[NB*LATD];
__device__ float g_zlat[NB*LATD];
__device__ float g_acc[2];
__device__ unsigned g_bar;

// ---------------- helpers ----------------
__device__ __forceinline__ void mma_bf16(float c[4], const unsigned a[4], const unsigned b[2]) {
    asm volatile(
        "mma.sync.aligned.m16n8k16.row.col.f32.bf16.bf16.f32 "
        "{%0,%1,%2,%3}, {%4,%5,%6,%7}, {%8,%9}, {%0,%1,%2,%3};\n"
        : "+f"(c[0]), "+f"(c[1]), "+f"(c[2]), "+f"(c[3])
        : "r"(a[0]), "r"(a[1]), "r"(a[2]), "r"(a[3]), "r"(b[0]), "r"(b[1]));
}
__device__ __forceinline__ float sigm(float x) { return 1.f / (1.f + expf(-x)); }

// ---------------- utility kernels ----------------
__global__ void k_zero(float* p, int n) {
    int i = blockIdx.x * blockDim.x + threadIdx.x;
    if (i < n) p[i] = 0.f;
}
__global__ void k_reset_bar(unsigned* b) { *b = 0u; }

// build encoder input rows (bf16, zero-padded to 512)
__global__ void k_build_enc(const int* __restrict__ X, const float* __restrict__ emb,
                            const float* __restrict__ C, __nv_bfloat16* __restrict__ out) {
    int bt = blockIdx.x;
    int b = bt / NT;
    __nv_bfloat16* row = out + (size_t)bt * UU;
    int x = X[bt];
    for (int i = threadIdx.x; i < UU; i += blockDim.x) {
        float v = 0.f;
        if (i < LATD) v = emb[x * LATD + i];
        else if (i < LATD + PP) v = C[b * PP + (i - LATD)];
        row[i] = __float2bfloat16_rn(v);
    }
}
__global__ void k_build_dec(const int* __restrict__ X, const float* __restrict__ emb,
                            const float* __restrict__ C, const float* __restrict__ zl,
                            __nv_bfloat16* __restrict__ out) {
    int bt = blockIdx.x;
    int b = bt / NT;
    __nv_bfloat16* row = out + (size_t)bt * UU;
    int x = X[bt];
    for (int i = threadIdx.x; i < UU; i += blockDim.x) {
        float v = 0.f;
        if (i < LATD) v = zl[b * LATD + i];
        else if (i < 2 * LATD) v = emb[x * LATD + (i - LATD)];
        else if (i < 2 * LATD + PP) v = C[b * PP + (i - 2 * LATD)];
        row[i] = __float2bfloat16_rn(v);
    }
}

// transpose+convert: W fp32 [K][2048] -> Wt bf16 [2048][512] (k zero-padded)
__global__ void k_convT(const float* __restrict__ W, int K, __nv_bfloat16* __restrict__ Wt) {
    __shared__ float tile[32][33];
    int nb0 = blockIdx.x * 32;   // 64 blocks
    int kb0 = blockIdx.y * 32;   // 16 blocks
    for (int i = threadIdx.x; i < 1024; i += blockDim.x) {
        int r = i >> 5, c = i & 31;   // r = k, c = n
        tile[r][c] = (kb0 + r < K) ? W[(size_t)(kb0 + r) * G4U + nb0 + c] : 0.f;
    }
    __syncthreads();
    for (int i = threadIdx.x; i < 1024; i += blockDim.x) {
        int r = i >> 5, c = i & 31;   // r = n, c = k
        Wt[(size_t)(nb0 + r) * UU + kb0 + c] = __float2bfloat16_rn(tile[c][r]);
    }
}

// ---------------- big GEMM: Z[M,2048] = A[M,512]bf16 @ Wt^T + bias ----------------
// 128x128 tile, k-chunks of 64, 8 warps (4m x 2n)
__global__ __launch_bounds__(256) void k_gemm_bf16(
    const __nv_bfloat16* __restrict__ A, const __nv_bfloat16* __restrict__ Wt,
    const float* __restrict__ bias, float* __restrict__ Co) {
    __shared__ __nv_bfloat16 As[128][72];   // [m][k]
    __shared__ __nv_bfloat16 Bs[128][72];   // [n][k]
    int tid = threadIdx.x;
    int wid = tid >> 5, lane = tid & 31;
    int wm = wid >> 1, wn = wid & 1;
    int lq = lane >> 2, lr = lane & 3;
    int row0 = blockIdx.y * 128, col0 = blockIdx.x * 128;

    float c[2][8][4];
#pragma unroll
    for (int mt = 0; mt < 2; mt++)
#pragma unroll
        for (int nt = 0; nt < 8; nt++)
#pragma unroll
            for (int j = 0; j < 4; j++) c[mt][nt][j] = 0.f;

    for (int kk = 0; kk < UU; kk += 64) {
#pragma unroll
        for (int i = tid; i < 1024; i += 256) {
            int r = i >> 3, c8 = (i & 7) * 8;
            *(uint4*)&As[r][c8] = *(const uint4*)&A[(size_t)(row0 + r) * UU + kk + c8];
            *(uint4*)&Bs[r][c8] = *(const uint4*)&Wt[(size_t)(col0 + r) * UU + kk + c8];
        }
        __syncthreads();
#pragma unroll
        for (int ks = 0; ks < 4; ks++) {
            int kb = ks * 16;
            unsigned af[2][4];
#pragma unroll
            for (int mt = 0; mt < 2; mt++) {
                int mb = wm * 32 + mt * 16;
                af[mt][0] = *(const unsigned*)&As[mb + lq][kb + 2 * lr];
                af[mt][1] = *(const unsigned*)&As[mb + lq + 8][kb + 2 * lr];
                af[mt][2] = *(const unsigned*)&As[mb + lq][kb + 8 + 2 * lr];
                af[mt][3] = *(const unsigned*)&As[mb + lq + 8][kb + 8 + 2 * lr];
            }
#pragma unroll
            for (int nt = 0; nt < 8; nt++) {
                int nb = wn * 64 + nt * 8;
                unsigned bf[2];
                bf[0] = *(const unsigned*)&Bs[nb + lq][kb + 2 * lr];
                bf[1] = *(const unsigned*)&Bs[nb + lq][kb + 8 + 2 * lr];
#pragma unroll
                for (int mt = 0; mt < 2; mt++) mma_bf16(c[mt][nt], af[mt], bf);
            }
        }
        __syncthreads();
    }
#pragma unroll
    for (int mt = 0; mt < 2; mt++) {
        size_t rb = (size_t)(row0 + wm * 32 + mt * 16 + lq);
#pragma unroll
        for (int nt = 0; nt < 8; nt++) {
            int cb = col0 + wn * 64 + nt * 8 + 2 * lr;
            float b0 = bias[cb], b1 = bias[cb + 1];
            Co[rb * G4U + cb]           = c[mt][nt][0] + b0;
            Co[rb * G4U + cb + 1]       = c[mt][nt][1] + b1;
            Co[(rb + 8) * G4U + cb]     = c[mt][nt][2] + b0;
            Co[(rb + 8) * G4U + cb + 1] = c[mt][nt][3] + b1;
        }
    }
}

// ---------------- persistent layer scan ----------------
// grid (16,8) = 128 blocks, ALL timesteps inside, grid barrier between steps.
// block owns (u0:u0+32, b0:b0+32); c kept in smem across steps.
__global__ __launch_bounds__(256) void k_scan(
    const float* __restrict__ Z, const __nv_bfloat16* __restrict__ rkt,
    __nv_bfloat16* __restrict__ hseq, float* __restrict__ cfin, unsigned* bar) {
    extern __shared__ char smraw[];
    __nv_bfloat16* hA = (__nv_bfloat16*)smraw;                         // [32][520]
    __nv_bfloat16* Bs = (__nv_bfloat16*)(smraw + 32 * 520 * 2);        // [128][136]
    float* zsm = (float*)(smraw + 32 * 520 * 2 + 128 * 136 * 2);       // [32][132]
    float* csm = zsm + 32 * 132;                                       // [32][32]

    int tid = threadIdx.x;
    int wid = tid >> 5, lane = tid & 31;
    int wm = wid >> 2, wn = wid & 3;
    int lq = lane >> 2, lr = lane & 3;
    int u0 = blockIdx.x * 32;
    int b0 = blockIdx.y * 32;

    for (int i = tid; i < 1024; i += 256) csm[i] = 0.f;
    __syncthreads();

    for (int t = 0; t < NT; t++) {
        float acc[4][4];
#pragma unroll
        for (int nt = 0; nt < 4; nt++)
#pragma unroll
            for (int j = 0; j < 4; j++) acc[nt][j] = 0.f;

        if (t > 0) {
            // ---- grid barrier ----
            __threadfence();
            __syncthreads();
            if (tid == 0) {
                atomicAdd(bar, 1u);
                unsigned target = (unsigned)t * SCAN_BLOCKS;
                while (atomicAdd(bar, 0u) < target) {}
            }
            __syncthreads();
            // load hA = h(t-1)[b0:b0+32][0:512]
            for (int i = tid; i < 2048; i += 256) {
                int r = i >> 6, c8 = (i & 63) * 8;
                *(uint4*)&hA[r * 520 + c8] =
                    *(const uint4*)&hseq[((size_t)(b0 + r) * NT + (t - 1)) * UU + c8];
            }
            for (int kc = 0; kc < 4; kc++) {
                int kk = kc * 128;
                for (int i = tid; i < 2048; i += 256) {
                    int n = i >> 4, c8 = (i & 15) * 8;
                    int g = n >> 5, ul = n & 31;
                    *(uint4*)&Bs[n * 136 + c8] =
                        *(const uint4*)&rkt[(size_t)(g * 512 + u0 + ul) * UU + kk + c8];
                }
                __syncthreads();
                int mb = wm * 16;
#pragma unroll
                for (int ks = 0; ks < 8; ks++) {
                    int kb = ks * 16;
                    unsigned af[4];
                    af[0] = *(const unsigned*)&hA[(mb + lq) * 520 + kk + kb + 2 * lr];
                    af[1] = *(const unsigned*)&hA[(mb + lq + 8) * 520 + kk + kb + 2 * lr];
                    af[2] = *(const unsigned*)&hA[(mb + lq) * 520 + kk + kb + 8 + 2 * lr];
                    af[3] = *(const unsigned*)&hA[(mb + lq + 8) * 520 + kk + kb + 8 + 2 * lr];
#pragma unroll
                    for (int nt = 0; nt < 4; nt++) {
                        int nb = wn * 32 + nt * 8;
                        unsigned bf[2];
                        bf[0] = *(const unsigned*)&Bs[(nb + lq) * 136 + kb + 2 * lr];
                        bf[1] = *(const unsigned*)&Bs[(nb + lq) * 136 + kb + 8 + 2 * lr];
                        mma_bf16(acc[nt], af, bf);
                    }
                }
                __syncthreads();
            }
        }

        // scatter gate preacts to zsm[32][132]  (col = gate*32 + ulocal)
        {
            int rb = wm * 16 + lq;
#pragma unroll
            for (int nt = 0; nt < 4; nt++) {
                int cb = wn * 32 + nt * 8 + 2 * lr;
                zsm[rb * 132 + cb]           = acc[nt][0];
                zsm[rb * 132 + cb + 1]       = acc[nt][1];
                zsm[(rb + 8) * 132 + cb]     = acc[nt][2];
                zsm[(rb + 8) * 132 + cb + 1] = acc[nt][3];
            }
        }
        __syncthreads();

        // LSTM update
#pragma unroll
        for (int rep = 0; rep < 4; rep++) {
            int e = rep * 256 + tid;
            int bl = e >> 5, ul = e & 31;
            int b = b0 + bl, u = u0 + ul;
            const float* zr = Z + ((size_t)b * NT + t) * G4U + u0 + ul;
            float zi = zsm[bl * 132 + ul]       + zr[0];
            float zf = zsm[bl * 132 + 32 + ul]  + zr[512];
            float zg = zsm[bl * 132 + 64 + ul]  + zr[1024];
            float zo = zsm[bl * 132 + 96 + ul]  + zr[1536];
            float co = csm[bl * 32 + ul];
            float c2 = sigm(zf) * co + sigm(zi) * tanhf(zg);
            float h2 = sigm(zo) * tanhf(c2);
            csm[bl * 32 + ul] = c2;
            hseq[((size_t)b * NT + t) * UU + u] = __float2bfloat16_rn(h2);
        }
        __syncthreads();
    }
    // final cell state
#pragma unroll
    for (int rep = 0; rep < 4; rep++) {
        int e = rep * 256 + tid;
        int bl = e >> 5, ul = e & 31;
        cfin[(b0 + bl) * UU + u0 + ul] = csm[bl * 32 + ul];
    }
}

// ---------------- mean / log_sigma / reparameterize ----------------
__global__ void k_mean_ls(const float* __restrict__ cst,
                          const float* __restrict__ Wm, const float* __restrict__ bm,
                          const float* __restrict__ Ws, const float* __restrict__ bs,
                          const float* __restrict__ eps,
                          float* __restrict__ mo, float* __restrict__ lo, float* __restrict__ zo) {
    int idx = blockIdx.x * blockDim.x + threadIdx.x;
    if (idx >= NB * LATD) return;
    int b = idx / LATD, l = idx % LATD;
    const float* cr = cst + b * UU;
    float m = bm[l], s = bs[l];
    for (int k = 0; k < UU; k++) {
        float cv = cr[k];
        m += cv * Wm[k * LATD + l];
        s += cv * Ws[k * LATD + l];
    }
    mo[idx] = m;
    lo[idx] = s;
    zo[idx] = m + expf(0.5f * s) * eps[idx];
}

__global__ void k_latent(const float* __restrict__ mo, const float* __restrict__ lo,
                         float* __restrict__ acc) {
    __shared__ float sdata[256];
    int idx = blockIdx.x * blockDim.x + threadIdx.x;
    float v = 0.f;
    if (idx < NB * LATD) {
        float m = mo[idx], s = lo[idx];
        v = 1.f + s - m * m - expf(s);
    }
    sdata[threadIdx.x] = v;
    __syncthreads();
    for (int o = 128; o > 0; o >>= 1) {
        if (threadIdx.x < o) sdata[threadIdx.x] += sdata[threadIdx.x + o];
        __syncthreads();
    }
    if (threadIdx.x == 0) atomicAdd(acc + 1, sdata[0]);
}

// ---------------- fused logits + log-softmax + masked CE ----------------
__global__ void k_ce(const __nv_bfloat16* __restrict__ H, const float* __restrict__ Wo,
                     const float* __restrict__ bo, const int* __restrict__ Y,
                     const int* __restrict__ L, float* __restrict__ acc) {
    __shared__ float hs[8][UU];
    int row0 = blockIdx.x * 8;
    for (int i = threadIdx.x; i < 8 * UU; i += 256) {
        int r = i >> 9, k = i & 511;
        hs[r][k] = __bfloat162float(H[(size_t)(row0 + r) * UU + k]);
    }
    __syncthreads();
    int w = threadIdx.x >> 5, lane = threadIdx.x & 31;
    int row = row0 + w;
    int b = row / NT, t = row % NT;

    float d0 = 0.f, d1 = 0.f;
    bool has1 = (lane + 32) < VOC;
    for (int k = 0; k < UU; k++) {
        float hv = hs[w][k];
        d0 += hv * Wo[k * VOC + lane];
        if (has1) d1 += hv * Wo[k * VOC + lane + 32];
    }
    float p0 = d0 + bo[lane];
    float p1 = has1 ? (d1 + bo[lane + 32]) : -1e30f;
    float m = fmaxf(p0, p1);
#pragma unroll
    for (int o = 16; o; o >>= 1) m = fmaxf(m, __shfl_xor_sync(0xffffffffu, m, o));
    float e = expf(p0 - m) + (has1 ? expf(p1 - m) : 0.f);
#pragma unroll
    for (int o = 16; o; o >>= 1) e += __shfl_xor_sync(0xffffffffu, e, o);
    float lse = logf(e) + m;
    int y = Y[row];
    float py = __shfl_sync(0xffffffffu, (y < 32) ? p0 : p1, y & 31);
    if (lane == 0) {
        float wt = (t < L[b]) ? 1.f : 0.f;
        atomicAdd(acc, (lse - py) * wt);
    }
}

__global__ void k_final(const float* __restrict__ acc, float* __restrict__ out, int out_size) {
    if (threadIdx.x == 0) {
        float recon = acc[0] / (float)BT;
        float lat = -0.5f * acc[1] / (float)(NB * LATD);
        if (out_size > 0) out[0] = recon + lat;
        if (out_size > 1) out[1] = recon;
        if (out_size > 2) out[2] = lat;
    }
}

// ---------------- host driver ----------------
#define SMEM_SCAN (32*520*2 + 128*136*2 + 32*132*4 + 32*32*4)

extern "C" void kernel_launch(void* const* d_in, const int* in_sizes, int n_in,
                              void* d_out, int out_size) {
    const int*   X       = (const int*)d_in[0];
    const int*   Y       = (const int*)d_in[1];
    const float* C       = (const float*)d_in[2];
    const int*   L       = (const int*)d_in[3];
    const float* eps     = (const float*)d_in[4];
    const float* emb_enc = (const float*)d_in[5];
    const float* emb_dec = (const float*)d_in[6];
    const float* enc_k[3]  = {(const float*)d_in[7],  (const float*)d_in[10], (const float*)d_in[13]};
    const float* enc_rk[3] = {(const float*)d_in[8],  (const float*)d_in[11], (const float*)d_in[14]};
    const float* enc_b[3]  = {(const float*)d_in[9],  (const float*)d_in[12], (const float*)d_in[15]};
    const float* dec_k[3]  = {(const float*)d_in[16], (const float*)d_in[19], (const float*)d_in[22]};
    const float* dec_rk[3] = {(const float*)d_in[17], (const float*)d_in[20], (const float*)d_in[23]};
    const float* dec_b[3]  = {(const float*)d_in[18], (const float*)d_in[21], (const float*)d_in[24]};
    const float* Wm = (const float*)d_in[25];
    const float* bm = (const float*)d_in[26];
    const float* Ws = (const float*)d_in[27];
    const float* bs = (const float*)d_in[28];
    const float* Wo = (const float*)d_in[29];
    const float* bo = (const float*)d_in[30];

    __nv_bfloat16 *bufA, *bufB, *wt, *rkt;
    float *Zb, *cst, *mo, *lo, *zl, *acc;
    unsigned* bar;
    cudaGetSymbolAddress((void**)&bufA, g_bufA);
    cudaGetSymbolAddress((void**)&bufB, g_bufB);
    cudaGetSymbolAddress((void**)&wt,   g_wt);
    cudaGetSymbolAddress((void**)&rkt,  g_rkt);
    cudaGetSymbolAddress((void**)&Zb,   g_Z);
    cudaGetSymbolAddress((void**)&cst,  g_c);
    cudaGetSymbolAddress((void**)&mo,   g_mean);
    cudaGetSymbolAddress((void**)&lo,   g_ls);
    cudaGetSymbolAddress((void**)&zl,   g_zlat);
    cudaGetSymbolAddress((void**)&acc,  g_acc);
    cudaGetSymbolAddress((void**)&bar,  g_bar);

    static int smem_set = 0;
    if (!smem_set) {
        cudaFuncSetAttribute(k_scan, cudaFuncAttributeMaxDynamicSharedMemorySize, SMEM_SCAN);
        smem_set = 1;
    }

    k_zero<<<1, 64>>>(acc, 2);

    dim3 gemm_grid(G4U / 128, BT / 128);
    dim3 conv_grid(64, 16);
    dim3 scan_grid(16, 8);

    const int encKs[3] = {LATD + PP, UU, UU};
    const int decKs[3] = {2 * LATD + PP, UU, UU};

    // ======== encoder ========
    k_build_enc<<<BT, 256>>>(X, emb_enc, C, bufA);
    {
        __nv_bfloat16* inb = bufA;
        __nv_bfloat16* outb = bufB;
        for (int l = 0; l < 3; l++) {
            k_convT<<<conv_grid, 256>>>(enc_k[l], encKs[l], wt);
            k_gemm_bf16<<<gemm_grid, 256>>>(inb, wt, enc_b[l], Zb);
            k_convT<<<conv_grid, 256>>>(enc_rk[l], UU, rkt);
            k_reset_bar<<<1, 1>>>(bar);
            k_scan<<<scan_grid, 256, SMEM_SCAN>>>(Zb, rkt, outb, cst, bar);
            __nv_bfloat16* tmp = inb; inb = outb; outb = tmp;
        }
    }
    k_mean_ls<<<(NB * LATD + 255) / 256, 256>>>(cst, Wm, bm, Ws, bs, eps, mo, lo, zl);
    k_latent<<<(NB * LATD + 255) / 256, 256>>>(mo, lo, acc);

    // ======== decoder ========
    k_build_dec<<<BT, 256>>>(X, emb_dec, C, zl, bufA);
    __nv_bfloat16* dec_h = nullptr;
    {
        __nv_bfloat16* inb = bufA;
        __nv_bfloat16* outb = bufB;
        for (int l = 0; l < 3; l++) {
            k_convT<<<conv_grid, 256>>>(dec_k[l], decKs[l], wt);
            k_gemm_bf16<<<gemm_grid, 256>>>(inb, wt, dec_b[l], Zb);
            k_convT<<<conv_grid, 256>>>(dec_rk[l], UU, rkt);
            k_reset_bar<<<1, 1>>>(bar);
            k_scan<<<scan_grid, 256, SMEM_SCAN>>>(Zb, rkt, outb, cst, bar);
            __nv_bfloat16* tmp = inb; inb = outb; outb = tmp;
        }
        dec_h = inb;
    }

    // ======== losses ========
    k_ce<<<BT / 8, 256>>>(dec_h, Wo, bo, Y, L, acc);
    k_final<<<1, 32>>>(acc, (float*)d_out, out_size);
}